// round 7
// baseline (speedup 1.0000x reference)
#include <cuda_runtime.h>
#include <cuda_fp16.h>
#include <mma.h>
#include <cstdint>

using namespace nvcuda;

#define NMAX 200000
#define D 128
#define LDH 136   // hA / Wa-slot leading dim (halves)
#define LDR 72    // rS / Wb-slot leading dim (halves)
#define LDF 68    // fS leading dim (floats)
#define LDP 132   // park leading dim (floats)

// smem (halves): hA 17408 | rS 9216 | fS 17408(h-equiv) | 4 slots x 9216
#define HA_OFF 0
#define RS_OFF 17408
#define FS_OFF 26624
#define SL_OFF 44032
#define SL_SZ  9216
static const int SMEM_BYTES = (SL_OFF + 4 * SL_SZ) * 2;  // 161792 B

__device__ float g_h[(size_t)NMAX * D];
__device__ float g_z[NMAX];
__device__ float g_deg[NMAX];
__device__ float g_dis[NMAX];
__device__ float g_u[NMAX];
__device__ float g_t[NMAX];
__device__ __half g_wh[1622016];  // [W1 3x262144 | W2 3x262144 | Wc 3x16384]
__device__ float g_bc[384];
#define OW1 0
#define OW2 786432
#define OWC 1572864

// ---------------------------------------------------------------------------
__device__ __forceinline__ void cp16h(__half* dst_smem, const __half* src) {
    unsigned int d = (unsigned int)__cvta_generic_to_shared(dst_smem);
    asm volatile("cp.async.cg.shared.global [%0], [%1], 16;\n" :: "r"(d), "l"(src));
}
__device__ __forceinline__ void cp_commit() { asm volatile("cp.async.commit_group;\n"); }
template <int NPEND>
__device__ __forceinline__ void cp_wait() { asm volatile("cp.async.wait_group %0;\n" :: "n"(NPEND)); }

// ---------------------------------------------------------------------------
__global__ void k_cvt_h(const float* __restrict__ src, __half* __restrict__ dst, int n) {
    int i = blockIdx.x * blockDim.x + threadIdx.x;
    if (i < n) dst[i] = __float2half_rn(src[i]);
}

__global__ void k_wc(const float* __restrict__ Wo, const float* __restrict__ Wv) {
    int l = blockIdx.x >> 7, o = blockIdx.x & 127, d = threadIdx.x;
    const float* wo = Wo + (size_t)(l * 128 + o) * 128;
    const float* wv = Wv + (size_t)l * 128 * 128;
    float s = 0.f;
#pragma unroll 8
    for (int k = 0; k < 128; k++) s += wo[k] * wv[k * 128 + d];
    g_wh[OWC + (size_t)(l * 128 + o) * 128 + d] = __float2half_rn(s);
}

__global__ void k_bc2(const float* __restrict__ Wo, const float* __restrict__ bv,
                      const float* __restrict__ bo) {
    int wid = (blockIdx.x * blockDim.x + threadIdx.x) >> 5;
    int lane = threadIdx.x & 31;
    if (wid >= 384) return;
    int l = wid >> 7;
    const float* wo = Wo + (size_t)wid * 128;
    float s = 0.f;
#pragma unroll
    for (int q = 0; q < 4; q++) s += wo[lane + q * 32] * bv[l * 128 + lane + q * 32];
#pragma unroll
    for (int o = 16; o; o >>= 1) s += __shfl_xor_sync(0xffffffffu, s, o);
    if (lane == 0) g_bc[wid] = s + bo[wid];
}

__global__ void k_input(const float* __restrict__ x, const float* __restrict__ Win,
                        const float* __restrict__ b_in, int N) {
    int idx = blockIdx.x * blockDim.x + threadIdx.x;
    if (idx >= N * D) return;
    int n = idx >> 7, d = idx & 127;
    float v = b_in[d] + x[n * 3 + 0] * Win[d * 3 + 0]
                      + x[n * 3 + 1] * Win[d * 3 + 1]
                      + x[n * 3 + 2] * Win[d * 3 + 2];
    g_h[idx] = fmaxf(v, 0.f);
}

// ---------------------------------------------------------------------------
// Fused sublayer (fp16 wmma, fp32 accum). 256 threads = 8 warps.
// Warp w: rows (w>>1)*32..+32, col half wc=w&1 (stage2 cols wc*64..+64).
// single==0: h = LN(h + Wb @ relu(Wa @ h + ba) + bb)
// single==1: h = LN(h + Wa @ h + bb)   (Wa = Wo@Wv precombined)
__global__ __launch_bounds__(256, 1)
void fused_layer_kernel(const __half* __restrict__ Wa, const float* __restrict__ ba,
                        const __half* __restrict__ Wb, const float* __restrict__ bb,
                        const float* __restrict__ lng, const float* __restrict__ lnb,
                        int F, int single, int N) {
    extern __shared__ __half smem[];
    __half* hA = smem + HA_OFF;
    __half* rS = smem + RS_OFF;
    float*  fS = (float*)(smem + FS_OFF);
    float*  parkF = (float*)(smem + FS_OFF);

    const int tid  = threadIdx.x;
    const int w    = tid >> 5;
    const int lane = tid & 31;
    const int wr   = w >> 1;
    const int wc   = w & 1;
    const int r0   = wr * 32;
    const int row0 = blockIdx.x * 128;

    typedef wmma::fragment<wmma::matrix_a, 16, 16, 16, __half, wmma::row_major> FragA;
    typedef wmma::fragment<wmma::matrix_b, 16, 16, 16, __half, wmma::col_major> FragB;
    typedef wmma::fragment<wmma::accumulator, 16, 16, 16, float> FragC;

    // ---- initial weight prefetch ----
    if (single) {
        // Wc [128 o][128 d] -> slot ch holds k-cols ch*64..+64 as [128][LDR]
        for (int i = tid; i < 2048; i += 256) {
            int ch = i >> 10, r = (i >> 3) & 127, s = i & 7;
            cp16h(smem + SL_OFF + ch * SL_SZ + r * LDR + s * 8,
                  Wa + (size_t)r * 128 + ch * 64 + s * 8);
        }
    } else {
        for (int i = tid; i < 1024; i += 256) {  // Wa[0]: [64 f][128 d] -> slot0
            int r = i >> 4, s = i & 15;
            cp16h(smem + SL_OFF + r * LDH + s * 8, Wa + (size_t)r * 128 + s * 8);
        }
        for (int i = tid; i < 1024; i += 256) {  // Wb[0]: [128 d2][64 f] -> slot1
            int r = i >> 3, s = i & 7;
            cp16h(smem + SL_OFF + SL_SZ + r * LDR + s * 8, Wb + (size_t)r * F + s * 8);
        }
    }
    cp_commit();

    // stage input rows as fp16 while copies fly
    for (int i = tid; i < 128 * 128; i += 256) {
        int r = i >> 7, c = i & 127;
        int gr = row0 + r;
        float v = (gr < N) ? g_h[(size_t)gr * D + c] : 0.f;
        hA[r * LDH + c] = __float2half_rn(v);
    }

    FragC acc[2][4];
#pragma unroll
    for (int i = 0; i < 2; i++)
#pragma unroll
        for (int j = 0; j < 4; j++) wmma::fill_fragment(acc[i][j], 0.f);

    if (single) {
        cp_wait<0>();
        __syncthreads();
#pragma unroll
        for (int ch = 0; ch < 2; ch++) {
            const __half* bufB = smem + SL_OFF + ch * SL_SZ;
#pragma unroll
            for (int kk = 0; kk < 4; kk++) {
                FragA aF[2];
#pragma unroll
                for (int i = 0; i < 2; i++)
                    wmma::load_matrix_sync(aF[i], hA + (r0 + i * 16) * LDH + ch * 64 + kk * 16, LDH);
#pragma unroll
                for (int jj = 0; jj < 4; jj++) {
                    FragB bF;
                    wmma::load_matrix_sync(bF, bufB + (wc * 64 + jj * 16) * LDR + kk * 16, LDR);
#pragma unroll
                    for (int i = 0; i < 2; i++) wmma::mma_sync(acc[i][jj], aF[i], bF, acc[i][jj]);
                }
            }
        }
    } else {
        const int nch = F >> 6;
        for (int ch = 0; ch < nch; ch++) {
            const int f0 = ch << 6;
            const __half* bufA = smem + SL_OFF + (2 * (ch & 1) + 0) * SL_SZ;
            const __half* bufB = smem + SL_OFF + (2 * (ch & 1) + 1) * SL_SZ;

            cp_wait<0>();
            __syncthreads();   // weights[ch] visible; prev stage2 done (slot/rS WAR safe)

            if (ch + 1 < nch) {
                __half* nA = smem + SL_OFF + (2 * ((ch + 1) & 1) + 0) * SL_SZ;
                __half* nB = smem + SL_OFF + (2 * ((ch + 1) & 1) + 1) * SL_SZ;
                const __half* srcA = Wa + (size_t)(f0 + 64) * 128;
                const __half* srcB = Wb + f0 + 64;
                for (int i = tid; i < 1024; i += 256) {
                    int r = i >> 4, s = i & 15;
                    cp16h(nA + r * LDH + s * 8, srcA + (size_t)r * 128 + s * 8);
                }
                for (int i = tid; i < 1024; i += 256) {
                    int r = i >> 3, s = i & 7;
                    cp16h(nB + r * LDR + s * 8, srcB + (size_t)r * F + s * 8);
                }
                cp_commit();
            } else {
                cp_commit();
            }

            // Stage 1: fS[r0:+32, wc*32:+32] = hA_rows @ WaChunk^T
            {
                FragC rf[2][2];
#pragma unroll
                for (int i = 0; i < 2; i++)
#pragma unroll
                    for (int j = 0; j < 2; j++) wmma::fill_fragment(rf[i][j], 0.f);
#pragma unroll
                for (int kk = 0; kk < 8; kk++) {
                    FragA aF[2];
#pragma unroll
                    for (int i = 0; i < 2; i++)
                        wmma::load_matrix_sync(aF[i], hA + (r0 + i * 16) * LDH + kk * 16, LDH);
#pragma unroll
                    for (int j = 0; j < 2; j++) {
                        FragB bF;
                        wmma::load_matrix_sync(bF, bufA + (wc * 32 + j * 16) * LDH + kk * 16, LDH);
#pragma unroll
                        for (int i = 0; i < 2; i++) wmma::mma_sync(rf[i][j], aF[i], bF, rf[i][j]);
                    }
                }
#pragma unroll
                for (int i = 0; i < 2; i++)
#pragma unroll
                    for (int j = 0; j < 2; j++)
                        wmma::store_matrix_sync(fS + (r0 + i * 16) * LDF + wc * 32 + j * 16,
                                                rf[i][j], LDF, wmma::mem_row_major);
            }
            __syncwarp();
            // bias + relu + fp16 into rS (warp-private 32x32 region)
            for (int t = lane; t < 32 * 32; t += 32) {
                int rr = t >> 5, cc = t & 31;
                float v = fS[(r0 + rr) * LDF + wc * 32 + cc] + ba[f0 + wc * 32 + cc];
                rS[(r0 + rr) * LDR + wc * 32 + cc] = __float2half_rn(fmaxf(v, 0.f));
            }
            // pair barrier: both col-half warps of this row group
            asm volatile("bar.sync %0, 64;" :: "r"(1 + wr) : "memory");

            // Stage 2: acc[r0:+32, wc*64:+64] += rS_rows @ WbChunk^T
#pragma unroll
            for (int kk = 0; kk < 4; kk++) {
                FragA aF[2];
#pragma unroll
                for (int i = 0; i < 2; i++)
                    wmma::load_matrix_sync(aF[i], rS + (r0 + i * 16) * LDR + kk * 16, LDR);
#pragma unroll
                for (int jj = 0; jj < 4; jj++) {
                    FragB bF;
                    wmma::load_matrix_sync(bF, bufB + (wc * 64 + jj * 16) * LDR + kk * 16, LDR);
#pragma unroll
                    for (int i = 0; i < 2; i++) wmma::mma_sync(acc[i][jj], aF[i], bF, acc[i][jj]);
                }
            }
        }
    }

    __syncthreads();   // all stage2 reads done; park area free
#pragma unroll
    for (int i = 0; i < 2; i++)
#pragma unroll
        for (int jj = 0; jj < 4; jj++)
            wmma::store_matrix_sync(parkF + (r0 + i * 16) * LDP + wc * 64 + jj * 16,
                                    acc[i][jj], LDP, wmma::mem_row_major);
    __syncthreads();

    // Epilogue: residual + bias + LayerNorm; warp handles 16 rows
    for (int i = 0; i < 16; i++) {
        int lr = w * 16 + i;
        int gr = row0 + lr;
        if (gr >= N) continue;
        float vals[4];
        float s = 0.f, sq = 0.f;
#pragma unroll
        for (int q = 0; q < 4; q++) {
            int c = lane + q * 32;
            float v = g_h[(size_t)gr * D + c] + parkF[lr * LDP + c] + bb[c];
            vals[q] = v;
            s += v; sq += v * v;
        }
#pragma unroll
        for (int o = 16; o; o >>= 1) {
            s  += __shfl_xor_sync(0xffffffffu, s, o);
            sq += __shfl_xor_sync(0xffffffffu, sq, o);
        }
        float m   = s * (1.f / 128.f);
        float var = sq * (1.f / 128.f) - m * m;
        float inv = rsqrtf(var + 1e-5f);
#pragma unroll
        for (int q = 0; q < 4; q++) {
            int c = lane + q * 32;
            g_h[(size_t)gr * D + c] = (vals[q] - m) * inv * lng[c] + lnb[c];
        }
    }
}

// ---------------------------------------------------------------------------
__global__ void k_head(const float* __restrict__ Wd, const float* __restrict__ bd, int N) {
    int warp = (blockIdx.x * blockDim.x + threadIdx.x) >> 5;
    int lane = threadIdx.x & 31;
    if (warp >= N) return;
    float s = 0.f;
#pragma unroll
    for (int q = 0; q < 4; q++) s += g_h[(size_t)warp * D + lane + q * 32] * Wd[lane + q * 32];
#pragma unroll
    for (int o = 16; o; o >>= 1) s += __shfl_xor_sync(0xffffffffu, s, o);
    if (lane == 0) g_z[warp] = fmaxf(s + bd[0], 0.f);
}

__global__ void k_deg_init(int N) {
    int n = blockIdx.x * blockDim.x + threadIdx.x;
    if (n < N) g_deg[n] = 1.0f;
}
__global__ void k_deg_count(const int* __restrict__ col, int E) {
    int e = blockIdx.x * blockDim.x + threadIdx.x;
    if (e < E) atomicAdd(&g_deg[col[e]], 1.0f);
}
__global__ void k_dis_u(int N) {
    int n = blockIdx.x * blockDim.x + threadIdx.x;
    if (n >= N) return;
    float dis = rsqrtf(fmaxf(g_deg[n], 1.0f));
    float u = g_z[n] * dis;
    g_dis[n] = dis;
    g_u[n] = u;
    g_t[n] = u;
}
__global__ void k_scatter(const int* __restrict__ row, const int* __restrict__ col, int E) {
    int e = blockIdx.x * blockDim.x + threadIdx.x;
    if (e < E) atomicAdd(&g_t[col[e]], g_u[row[e]]);
}
__global__ void k_out(const float* __restrict__ Wg, const float* __restrict__ bg,
                      const float* __restrict__ Wf, const float* __restrict__ bf,
                      float* __restrict__ out, int N) {
    int n = blockIdx.x * blockDim.x + threadIdx.x;
    if (n >= N) return;
    float s = g_dis[n] * g_t[n];
    float a = bf[0];
#pragma unroll
    for (int k = 0; k < 32; k++)
        a += fmaxf(s * Wg[k] + bg[k], 0.f) * Wf[k];
    out[n] = a;
}

// ---------------------------------------------------------------------------
extern "C" void kernel_launch(void* const* d_in, const int* in_sizes, int n_in,
                              void* d_out, int out_size) {
    const float* x    = (const float*)d_in[0];
    const int*   edge = (const int*)  d_in[1];
    const float* Win  = (const float*)d_in[2];
    const float* b_in = (const float*)d_in[3];
    const float* Wv   = (const float*)d_in[4];
    const float* bv   = (const float*)d_in[5];
    const float* Wo   = (const float*)d_in[6];
    const float* bo   = (const float*)d_in[7];
    const float* W1   = (const float*)d_in[8];
    const float* b1   = (const float*)d_in[9];
    const float* W2   = (const float*)d_in[10];
    const float* b2   = (const float*)d_in[11];
    const float* ln1g = (const float*)d_in[12];
    const float* ln1b = (const float*)d_in[13];
    const float* ln2g = (const float*)d_in[14];
    const float* ln2b = (const float*)d_in[15];
    const float* Wd   = (const float*)d_in[16];
    const float* bd   = (const float*)d_in[17];
    const float* Wg   = (const float*)d_in[18];
    const float* bg   = (const float*)d_in[19];
    const float* Wf   = (const float*)d_in[20];
    const float* bf   = (const float*)d_in[21];

    const int N = in_sizes[0] / 3;
    const int E = in_sizes[1] / 2;
    const int F = 2048;

    __half* wh;
    cudaGetSymbolAddress((void**)&wh, g_wh);
    float* bc;
    cudaGetSymbolAddress((void**)&bc, g_bc);

    cudaFuncSetAttribute(fused_layer_kernel,
                         cudaFuncAttributeMaxDynamicSharedMemorySize, SMEM_BYTES);

    k_cvt_h<<<(786432 + 255) / 256, 256>>>(W1, wh + OW1, 786432);
    k_cvt_h<<<(786432 + 255) / 256, 256>>>(W2, wh + OW2, 786432);
    k_wc<<<384, 128>>>(Wo, Wv);
    k_bc2<<<48, 256>>>(Wo, bv, bo);
    k_input<<<(N * D + 255) / 256, 256>>>(x, Win, b_in, N);

    const int blocks = (N + 127) / 128;
    for (int i = 0; i < 3; i++) {
        fused_layer_kernel<<<blocks, 256, SMEM_BYTES>>>(
            wh + OWC + (size_t)i * 16384, nullptr, nullptr,
            bc + i * 128, ln1g + i * D, ln1b + i * D,
            /*F=*/128, /*single=*/1, N);
        fused_layer_kernel<<<blocks, 256, SMEM_BYTES>>>(
            wh + OW1 + (size_t)i * (size_t)F * D, b1 + i * F,
            wh + OW2 + (size_t)i * (size_t)D * F, b2 + i * D,
            ln2g + i * D, ln2b + i * D, /*F=*/F, /*single=*/0, N);
    }

    k_head<<<(N + 7) / 8, 256>>>(Wd, bd, N);
    k_deg_init<<<(N + 255) / 256, 256>>>(N);
    k_deg_count<<<(E + 255) / 256, 256>>>(edge + E, E);
    k_dis_u<<<(N + 255) / 256, 256>>>(N);
    k_scatter<<<(E + 255) / 256, 256>>>(edge, edge + E, E);
    k_out<<<(N + 255) / 256, 256>>>(Wg, bg, Wf, bf, (float*)d_out, N);
}

// round 8
// speedup vs baseline: 1.6130x; 1.6130x over previous
#include <cuda_runtime.h>
#include <cuda_fp16.h>
#include <cstdint>

#define NMAX 200000
#define D 128
#define BR 256          // rows per block

// ---- smem layout (bytes) ----
#define HA_OFF    0        // hA: 256 rows x 272B (136 halves)        69632
#define RS_OFF    69632    // rS: 256 rows x 144B (72 halves)         36864
#define SLOTS_OFF 106496   // 2 pairs x (Wa 18432 + Wb 18432)         73728
#define BA_OFF    180224   // stage-1 bias, up to 2048 floats          8192
#define BB_OFF    188416   // final bias 128 f                          512
#define LNG_OFF   188928
#define LNB_OFF   189440
#define RED_OFF   189952   // LN partials: 256 rows x 2 x float2       4096
static const int SMEM_BYTES = 194048;
#define SL_PAIR 36864
#define SL_SZ   18432

__device__ float g_h[(size_t)NMAX * D];
__device__ float g_z[NMAX];
__device__ float g_deg[NMAX];
__device__ float g_dis[NMAX];
__device__ float g_u[NMAX];
__device__ float g_t[NMAX];
__device__ __half g_wh[1622016];  // [W1 3x262144 | W2 3x262144 | Wc 3x16384]
__device__ float g_bc[384];
#define OW1 0
#define OW2 786432
#define OWC 1572864

// ---------------------------------------------------------------------------
static __device__ __forceinline__ uint32_t smem_u32(const void* p) {
    uint32_t r;
    asm("{ .reg .u64 t; cvta.to.shared.u64 t, %1; cvt.u32.u64 %0, t; }" : "=r"(r) : "l"(p));
    return r;
}
static __device__ __forceinline__ void cp16h(uint32_t dst, const __half* src) {
    asm volatile("cp.async.cg.shared.global [%0], [%1], 16;\n" :: "r"(dst), "l"(src));
}
static __device__ __forceinline__ void cp_commit() { asm volatile("cp.async.commit_group;\n"); }
template <int NPEND>
static __device__ __forceinline__ void cp_wait() { asm volatile("cp.async.wait_group %0;\n" :: "n"(NPEND)); }

static __device__ __forceinline__ void ldsm4(uint32_t* r, uint32_t addr) {
    asm volatile("ldmatrix.sync.aligned.m8n8.x4.shared.b16 {%0,%1,%2,%3}, [%4];"
                 : "=r"(r[0]), "=r"(r[1]), "=r"(r[2]), "=r"(r[3]) : "r"(addr));
}
static __device__ __forceinline__ void mma16816(float* c, const uint32_t* a,
                                                uint32_t b0, uint32_t b1) {
    asm volatile("mma.sync.aligned.m16n8k16.row.col.f32.f16.f16.f32 "
                 "{%0,%1,%2,%3}, {%4,%5,%6,%7}, {%8,%9}, {%0,%1,%2,%3};"
                 : "+f"(c[0]), "+f"(c[1]), "+f"(c[2]), "+f"(c[3])
                 : "r"(a[0]), "r"(a[1]), "r"(a[2]), "r"(a[3]), "r"(b0), "r"(b1));
}

// ---------------------------------------------------------------------------
__global__ void k_cvt_h(const float* __restrict__ src, __half* __restrict__ dst, int n) {
    int i = blockIdx.x * blockDim.x + threadIdx.x;
    if (i < n) dst[i] = __float2half_rn(src[i]);
}

__global__ void k_wc(const float* __restrict__ Wo, const float* __restrict__ Wv) {
    int l = blockIdx.x >> 7, o = blockIdx.x & 127, d = threadIdx.x;
    const float* wo = Wo + (size_t)(l * 128 + o) * 128;
    const float* wv = Wv + (size_t)l * 128 * 128;
    float s = 0.f;
#pragma unroll 8
    for (int k = 0; k < 128; k++) s += wo[k] * wv[k * 128 + d];
    g_wh[OWC + (size_t)(l * 128 + o) * 128 + d] = __float2half_rn(s);
}

__global__ void k_bc2(const float* __restrict__ Wo, const float* __restrict__ bv,
                      const float* __restrict__ bo) {
    int wid = (blockIdx.x * blockDim.x + threadIdx.x) >> 5;
    int lane = threadIdx.x & 31;
    if (wid >= 384) return;
    int l = wid >> 7;
    const float* wo = Wo + (size_t)wid * 128;
    float s = 0.f;
#pragma unroll
    for (int q = 0; q < 4; q++) s += wo[lane + q * 32] * bv[l * 128 + lane + q * 32];
#pragma unroll
    for (int o = 16; o; o >>= 1) s += __shfl_xor_sync(0xffffffffu, s, o);
    if (lane == 0) g_bc[wid] = s + bo[wid];
}

__global__ void k_input(const float* __restrict__ x, const float* __restrict__ Win,
                        const float* __restrict__ b_in, int N) {
    int idx = blockIdx.x * blockDim.x + threadIdx.x;
    if (idx >= N * D) return;
    int n = idx >> 7, d = idx & 127;
    float v = b_in[d] + x[n * 3 + 0] * Win[d * 3 + 0]
                      + x[n * 3 + 1] * Win[d * 3 + 1]
                      + x[n * 3 + 2] * Win[d * 3 + 2];
    g_h[idx] = fmaxf(v, 0.f);
}

// ---------------------------------------------------------------------------
// mma.sync fused sublayer. 512 threads = 16 warps; warp: rows r0=(w>>1)*32, col half wc=w&1.
// single==0: h = LN(h + Wb @ relu(Wa @ h + ba) + bb)  Wa:[F,128], Wb:[128,F] fp16
// single==1: h = LN(h + Wa @ h + bb)                  Wa:[128,128] fp16 (Wo@Wv)
__global__ __launch_bounds__(512, 1)
void fused_mma(const __half* __restrict__ Wa, const float* __restrict__ ba,
               const __half* __restrict__ Wb, const float* __restrict__ bb,
               const float* __restrict__ lng, const float* __restrict__ lnb,
               int F, int single, int N) {
    extern __shared__ __align__(256) unsigned char smem[];
    const int tid = threadIdx.x, w = tid >> 5, lane = tid & 31;
    const int wr = w >> 1, wc = w & 1, r0 = wr * 32;
    const int row0 = blockIdx.x * BR;
    const uint32_t sb = smem_u32(smem);
    const int nch = F >> 6;

    float* baS  = (float*)(smem + BA_OFF);
    float* bbS  = (float*)(smem + BB_OFF);
    float* lngS = (float*)(smem + LNG_OFF);
    float* lnbS = (float*)(smem + LNB_OFF);
    float2* red = (float2*)(smem + RED_OFF);

    // ---- issue first weight copies ----
    if (single) {
        // Wc [128 o][128 k] -> SLOTS, stride 272
        for (int i = tid; i < 2048; i += 512) {
            int r = i >> 4, s = i & 15;
            cp16h(sb + SLOTS_OFF + r * 272 + s * 16, Wa + (size_t)r * 128 + s * 8);
        }
    } else {
        // chunk 0: Wa [64 f][128 k] stride 272 ; Wb [128 d2][64 f] stride 144
        for (int i = tid; i < 1024; i += 512) {
            int r = i >> 4, s = i & 15;
            cp16h(sb + SLOTS_OFF + r * 272 + s * 16, Wa + (size_t)r * 128 + s * 8);
        }
        for (int i = tid; i < 1024; i += 512) {
            int r = i >> 3, s = i & 7;
            cp16h(sb + SLOTS_OFF + SL_SZ + r * 144 + s * 16, Wb + (size_t)r * F + s * 8);
        }
    }
    cp_commit();

    // ---- stage hA (fp16), biases ----
    for (int i = tid; i < BR * 64; i += 512) {
        int r = i >> 6, j = i & 63;
        int gr = row0 + r;
        float2 v = make_float2(0.f, 0.f);
        if (gr < N) v = *(const float2*)(g_h + (size_t)gr * D + j * 2);
        __half2 h2 = __floats2half2_rn(v.x, v.y);
        *(uint32_t*)(smem + HA_OFF + r * 272 + j * 4) = *(uint32_t*)&h2;
    }
    if (!single)
        for (int i = tid; i < F; i += 512) baS[i] = ba[i];
    for (int i = tid; i < 128; i += 512) {
        bbS[i] = bb[i]; lngS[i] = lng[i]; lnbS[i] = lnb[i];
    }

    const uint32_t loff272 = (lane & 15) * 272 + (lane >> 4) * 16;
    const uint32_t loff144 = (lane & 15) * 144 + (lane >> 4) * 16;
    const uint32_t haA = sb + HA_OFF + r0 * 272 + loff272;

    float acc[2][8][4];
#pragma unroll
    for (int m = 0; m < 2; m++)
#pragma unroll
        for (int n = 0; n < 8; n++)
#pragma unroll
            for (int e = 0; e < 4; e++) acc[m][n][e] = 0.f;

    if (single) {
        cp_wait<0>();
        __syncthreads();
        const uint32_t bB = sb + SLOTS_OFF + (wc * 64) * 272 + loff272;
        uint32_t a[2][4], b[4][4];
#pragma unroll
        for (int kk = 0; kk < 8; kk++) {
            ldsm4(a[0], haA + kk * 32);
            ldsm4(a[1], haA + 16 * 272 + kk * 32);
#pragma unroll
            for (int g = 0; g < 4; g++) ldsm4(b[g], bB + g * 16 * 272 + kk * 32);
#pragma unroll
            for (int m = 0; m < 2; m++)
#pragma unroll
                for (int n = 0; n < 8; n++)
                    mma16816(acc[m][n], a[m], b[n >> 1][n & 1], b[n >> 1][(n & 1) + 2]);
        }
    } else {
        for (int ch = 0; ch < nch; ch++) {
            const int f0 = ch << 6;
            const uint32_t sWa = sb + SLOTS_OFF + (ch & 1) * SL_PAIR;
            const uint32_t sWb = sWa + SL_SZ;

            cp_wait<0>();
            __syncthreads();   // weights[ch] visible; rS + other slot pair WAR safe

            if (ch + 1 < nch) {
                uint32_t nWa = sb + SLOTS_OFF + ((ch + 1) & 1) * SL_PAIR;
                uint32_t nWb = nWa + SL_SZ;
                const __half* srcA = Wa + (size_t)(f0 + 64) * 128;
                const __half* srcB = Wb + (f0 + 64);
                for (int i = tid; i < 1024; i += 512) {
                    int r = i >> 4, s = i & 15;
                    cp16h(nWa + r * 272 + s * 16, srcA + (size_t)r * 128 + s * 8);
                }
                for (int i = tid; i < 1024; i += 512) {
                    int r = i >> 3, s = i & 7;
                    cp16h(nWb + r * 144 + s * 16, srcB + (size_t)r * F + s * 8);
                }
            }
            cp_commit();

            // ---- stage 1: rf[32 rows][32 cols] = hA @ WaChunk^T ----
            float rf[2][4][4];
#pragma unroll
            for (int m = 0; m < 2; m++)
#pragma unroll
                for (int n = 0; n < 4; n++)
#pragma unroll
                    for (int e = 0; e < 4; e++) rf[m][n][e] = 0.f;
            {
                const uint32_t bB = sWa + (wc * 32) * 272 + loff272;
                uint32_t a[2][4], b[2][4];
#pragma unroll
                for (int kk = 0; kk < 8; kk++) {
                    ldsm4(a[0], haA + kk * 32);
                    ldsm4(a[1], haA + 16 * 272 + kk * 32);
                    ldsm4(b[0], bB + kk * 32);
                    ldsm4(b[1], bB + 16 * 272 + kk * 32);
#pragma unroll
                    for (int m = 0; m < 2; m++)
#pragma unroll
                        for (int n = 0; n < 4; n++)
                            mma16816(rf[m][n], a[m], b[n >> 1][n & 1], b[n >> 1][(n & 1) + 2]);
                }
            }
            // ---- mid: bias + relu + pack fp16 -> rS (in registers) ----
#pragma unroll
            for (int m = 0; m < 2; m++)
#pragma unroll
                for (int n = 0; n < 4; n++) {
                    int c = wc * 32 + n * 8 + (lane & 3) * 2;
                    float2 bias = *(const float2*)&baS[f0 + c];
                    int rowb = r0 + m * 16 + (lane >> 2);
                    float h0 = fmaxf(rf[m][n][0] + bias.x, 0.f);
                    float h1 = fmaxf(rf[m][n][1] + bias.y, 0.f);
                    __half2 p0 = __floats2half2_rn(h0, h1);
                    *(uint32_t*)(smem + RS_OFF + rowb * 144 + c * 2) = *(uint32_t*)&p0;
                    float h2 = fmaxf(rf[m][n][2] + bias.x, 0.f);
                    float h3 = fmaxf(rf[m][n][3] + bias.y, 0.f);
                    __half2 p1 = __floats2half2_rn(h2, h3);
                    *(uint32_t*)(smem + RS_OFF + (rowb + 8) * 144 + c * 2) = *(uint32_t*)&p1;
                }
            asm volatile("bar.sync %0, 64;" :: "r"(1 + wr) : "memory");

            // ---- stage 2: acc += rS @ WbChunk^T ----
            {
                const uint32_t aB = sb + RS_OFF + r0 * 144 + loff144;
                const uint32_t bB = sWb + (wc * 64) * 144 + loff144;
                uint32_t a[2][4], b[4][4];
#pragma unroll
                for (int kk = 0; kk < 4; kk++) {
                    ldsm4(a[0], aB + kk * 32);
                    ldsm4(a[1], aB + 16 * 144 + kk * 32);
#pragma unroll
                    for (int g = 0; g < 4; g++) ldsm4(b[g], bB + g * 16 * 144 + kk * 32);
#pragma unroll
                    for (int m = 0; m < 2; m++)
#pragma unroll
                        for (int n = 0; n < 8; n++)
                            mma16816(acc[m][n], a[m], b[n >> 1][n & 1], b[n >> 1][(n & 1) + 2]);
                }
            }
        }
    }

    // ---- epilogue: residual + bias + LayerNorm, from acc registers ----
#pragma unroll
    for (int m = 0; m < 2; m++)
#pragma unroll
        for (int h = 0; h < 2; h++) {
            int lr = r0 + m * 16 + (lane >> 2) + h * 8;
            int gr = row0 + lr;
            float ss = 0.f, qq = 0.f;
            if (gr < N) {
#pragma unroll
                for (int n = 0; n < 8; n++) {
                    int c = wc * 64 + n * 8 + (lane & 3) * 2;
                    float2 ho = *(const float2*)(g_h + (size_t)gr * D + c);
                    float v0 = acc[m][n][h * 2 + 0] + ho.x + bbS[c];
                    float v1 = acc[m][n][h * 2 + 1] + ho.y + bbS[c + 1];
                    ss += v0 + v1;
                    qq += v0 * v0 + v1 * v1;
                }
            }
            ss += __shfl_xor_sync(0xffffffffu, ss, 1);
            ss += __shfl_xor_sync(0xffffffffu, ss, 2);
            qq += __shfl_xor_sync(0xffffffffu, qq, 1);
            qq += __shfl_xor_sync(0xffffffffu, qq, 2);
            if ((lane & 3) == 0) red[lr * 2 + wc] = make_float2(ss, qq);
        }
    asm volatile("bar.sync %0, 64;" :: "r"(1 + wr) : "memory");
#pragma unroll
    for (int m = 0; m < 2; m++)
#pragma unroll
        for (int h = 0; h < 2; h++) {
            int lr = r0 + m * 16 + (lane >> 2) + h * 8;
            int gr = row0 + lr;
            if (gr >= N) continue;
            float2 p0 = red[lr * 2 + 0], p1 = red[lr * 2 + 1];
            float mean = (p0.x + p1.x) * (1.f / 128.f);
            float inv = rsqrtf((p0.y + p1.y) * (1.f / 128.f) - mean * mean + 1e-5f);
#pragma unroll
            for (int n = 0; n < 8; n++) {
                int c = wc * 64 + n * 8 + (lane & 3) * 2;
                float2 ho = *(const float2*)(g_h + (size_t)gr * D + c);
                float v0 = acc[m][n][h * 2 + 0] + ho.x + bbS[c];
                float v1 = acc[m][n][h * 2 + 1] + ho.y + bbS[c + 1];
                float2 o;
                o.x = (v0 - mean) * inv * lngS[c] + lnbS[c];
                o.y = (v1 - mean) * inv * lngS[c + 1] + lnbS[c + 1];
                *(float2*)(g_h + (size_t)gr * D + c) = o;
            }
        }
}

// ---------------------------------------------------------------------------
__global__ void k_head(const float* __restrict__ Wd, const float* __restrict__ bd, int N) {
    int warp = (blockIdx.x * blockDim.x + threadIdx.x) >> 5;
    int lane = threadIdx.x & 31;
    if (warp >= N) return;
    float s = 0.f;
#pragma unroll
    for (int q = 0; q < 4; q++) s += g_h[(size_t)warp * D + lane + q * 32] * Wd[lane + q * 32];
#pragma unroll
    for (int o = 16; o; o >>= 1) s += __shfl_xor_sync(0xffffffffu, s, o);
    if (lane == 0) g_z[warp] = fmaxf(s + bd[0], 0.f);
}

__global__ void k_deg_init(int N) {
    int n = blockIdx.x * blockDim.x + threadIdx.x;
    if (n < N) g_deg[n] = 1.0f;
}
__global__ void k_deg_count(const int* __restrict__ col, int E) {
    int e = blockIdx.x * blockDim.x + threadIdx.x;
    if (e < E) atomicAdd(&g_deg[col[e]], 1.0f);
}
__global__ void k_dis_u(int N) {
    int n = blockIdx.x * blockDim.x + threadIdx.x;
    if (n >= N) return;
    float dis = rsqrtf(fmaxf(g_deg[n], 1.0f));
    float u = g_z[n] * dis;
    g_dis[n] = dis;
    g_u[n] = u;
    g_t[n] = u;
}
__global__ void k_scatter(const int* __restrict__ row, const int* __restrict__ col, int E) {
    int e = blockIdx.x * blockDim.x + threadIdx.x;
    if (e < E) atomicAdd(&g_t[col[e]], g_u[row[e]]);
}
__global__ void k_out(const float* __restrict__ Wg, const float* __restrict__ bg,
                      const float* __restrict__ Wf, const float* __restrict__ bf,
                      float* __restrict__ out, int N) {
    int n = blockIdx.x * blockDim.x + threadIdx.x;
    if (n >= N) return;
    float s = g_dis[n] * g_t[n];
    float a = bf[0];
#pragma unroll
    for (int k = 0; k < 32; k++)
        a += fmaxf(s * Wg[k] + bg[k], 0.f) * Wf[k];
    out[n] = a;
}

// ---------------------------------------------------------------------------
extern "C" void kernel_launch(void* const* d_in, const int* in_sizes, int n_in,
                              void* d_out, int out_size) {
    const float* x    = (const float*)d_in[0];
    const int*   edge = (const int*)  d_in[1];
    const float* Win  = (const float*)d_in[2];
    const float* b_in = (const float*)d_in[3];
    const float* Wv   = (const float*)d_in[4];
    const float* bv   = (const float*)d_in[5];
    const float* Wo   = (const float*)d_in[6];
    const float* bo   = (const float*)d_in[7];
    const float* W1   = (const float*)d_in[8];
    const float* b1   = (const float*)d_in[9];
    const float* W2   = (const float*)d_in[10];
    const float* b2   = (const float*)d_in[11];
    const float* ln1g = (const float*)d_in[12];
    const float* ln1b = (const float*)d_in[13];
    const float* ln2g = (const float*)d_in[14];
    const float* ln2b = (const float*)d_in[15];
    const float* Wd   = (const float*)d_in[16];
    const float* bd   = (const float*)d_in[17];
    const float* Wg   = (const float*)d_in[18];
    const float* bg   = (const float*)d_in[19];
    const float* Wf   = (const float*)d_in[20];
    const float* bf   = (const float*)d_in[21];

    const int N = in_sizes[0] / 3;
    const int E = in_sizes[1] / 2;
    const int F = 2048;

    __half* wh;
    cudaGetSymbolAddress((void**)&wh, g_wh);
    float* bc;
    cudaGetSymbolAddress((void**)&bc, g_bc);

    cudaFuncSetAttribute(fused_mma, cudaFuncAttributeMaxDynamicSharedMemorySize, SMEM_BYTES);

    k_cvt_h<<<(786432 + 255) / 256, 256>>>(W1, wh + OW1, 786432);
    k_cvt_h<<<(786432 + 255) / 256, 256>>>(W2, wh + OW2, 786432);
    k_wc<<<384, 128>>>(Wo, Wv);
    k_bc2<<<48, 256>>>(Wo, bv, bo);
    k_input<<<(N * D + 255) / 256, 256>>>(x, Win, b_in, N);

    const int blocks = (N + BR - 1) / BR;
    for (int i = 0; i < 3; i++) {
        fused_mma<<<blocks, 512, SMEM_BYTES>>>(
            wh + OWC + (size_t)i * 16384, nullptr, nullptr,
            bc + i * 128, ln1g + i * D, ln1b + i * D,
            /*F=*/128, /*single=*/1, N);
        fused_mma<<<blocks, 512, SMEM_BYTES>>>(
            wh + OW1 + (size_t)i * (size_t)F * D, b1 + i * F,
            wh + OW2 + (size_t)i * (size_t)D * F, b2 + i * D,
            ln2g + i * D, ln2b + i * D, /*F=*/F, /*single=*/0, N);
    }

    k_head<<<(N + 7) / 8, 256>>>(Wd, bd, N);
    k_deg_init<<<(N + 255) / 256, 256>>>(N);
    k_deg_count<<<(E + 255) / 256, 256>>>(edge + E, E);
    k_dis_u<<<(N + 255) / 256, 256>>>(N);
    k_scatter<<<(E + 255) / 256, 256>>>(edge, edge + E, E);
    k_out<<<(N + 255) / 256, 256>>>(Wg, bg, Wf, bf, (float*)d_out, N);
}

// round 9
// speedup vs baseline: 1.7920x; 1.1110x over previous
#include <cuda_runtime.h>
#include <cuda_fp16.h>
#include <cstdint>

#define NMAX 200000
#define D 128
#define BR 256
#define MAXT 800

// ---- smem layout (bytes) ----
#define HA_OFF    0        // hA: 256 x 272B
#define RS_OFF    69632    // rS: 256 x 144B
#define SLOTS_OFF 106496   // 2 pairs x (Wa 18432 + Wb 18432)
#define BA_OFF    180224   // stage-1 bias (FFN) / Win+b_in (s==0)
#define BB_OFF    188416
#define LNG_OFF   188928
#define LNB_OFF   189440
#define RED_OFF   189952   // LN partials float2[256][2]; xS staging (768 f) for s==0
#define ZRED_OFF  194048   // z partials float[256][2]
#define WD_OFF    196096   // Wd 128 floats + bd
#define ITEM_OFF  196616
static const int SMEM_BYTES = 196640;
#define SL_PAIR 36864
#define SL_SZ   18432

__device__ float g_h[(size_t)NMAX * D];
__device__ float g_z[NMAX];
__device__ float g_deg[NMAX];
__device__ float g_dis[NMAX];
__device__ float g_u[NMAX];
__device__ float g_t[NMAX];
__device__ __half g_wh[1622016];  // [W1 3x262144 | W2 3x262144 | Wc 3x16384]
__device__ float g_bc[384];
__device__ int g_ctr;
__device__ int g_done[6 * MAXT];
#define OW1 0
#define OW2 786432
#define OWC 1572864

// ---------------------------------------------------------------------------
static __device__ __forceinline__ uint32_t smem_u32(const void* p) {
    uint32_t r;
    asm("{ .reg .u64 t; cvta.to.shared.u64 t, %1; cvt.u32.u64 %0, t; }" : "=r"(r) : "l"(p));
    return r;
}
static __device__ __forceinline__ void cp16h(uint32_t dst, const __half* src) {
    asm volatile("cp.async.cg.shared.global [%0], [%1], 16;\n" :: "r"(dst), "l"(src));
}
static __device__ __forceinline__ void cp_commit() { asm volatile("cp.async.commit_group;\n"); }
template <int NPEND>
static __device__ __forceinline__ void cp_wait() { asm volatile("cp.async.wait_group %0;\n" :: "n"(NPEND)); }

static __device__ __forceinline__ void ldsm4(uint32_t* r, uint32_t addr) {
    asm volatile("ldmatrix.sync.aligned.m8n8.x4.shared.b16 {%0,%1,%2,%3}, [%4];"
                 : "=r"(r[0]), "=r"(r[1]), "=r"(r[2]), "=r"(r[3]) : "r"(addr));
}
static __device__ __forceinline__ void mma16816(float* c, const uint32_t* a,
                                                uint32_t b0, uint32_t b1) {
    asm volatile("mma.sync.aligned.m16n8k16.row.col.f32.f16.f16.f32 "
                 "{%0,%1,%2,%3}, {%4,%5,%6,%7}, {%8,%9}, {%0,%1,%2,%3};"
                 : "+f"(c[0]), "+f"(c[1]), "+f"(c[2]), "+f"(c[3])
                 : "r"(a[0]), "r"(a[1]), "r"(a[2]), "r"(a[3]), "r"(b0), "r"(b1));
}

// ---------------------------------------------------------------------------
__global__ void k_reset() {
    int i = blockIdx.x * blockDim.x + threadIdx.x;
    if (i == 0) g_ctr = 0;
    if (i < 6 * MAXT) g_done[i] = 0;
}

__global__ void k_cvt_h(const float* __restrict__ src, __half* __restrict__ dst, int n) {
    int i = blockIdx.x * blockDim.x + threadIdx.x;
    if (i < n) dst[i] = __float2half_rn(src[i]);
}

__global__ void k_wc(const float* __restrict__ Wo, const float* __restrict__ Wv) {
    int l = blockIdx.x >> 7, o = blockIdx.x & 127, d = threadIdx.x;
    const float* wo = Wo + (size_t)(l * 128 + o) * 128;
    const float* wv = Wv + (size_t)l * 128 * 128;
    float s = 0.f;
#pragma unroll 8
    for (int k = 0; k < 128; k++) s += wo[k] * wv[k * 128 + d];
    g_wh[OWC + (size_t)(l * 128 + o) * 128 + d] = __float2half_rn(s);
}

__global__ void k_bc2(const float* __restrict__ Wo, const float* __restrict__ bv,
                      const float* __restrict__ bo) {
    int wid = (blockIdx.x * blockDim.x + threadIdx.x) >> 5;
    int lane = threadIdx.x & 31;
    if (wid >= 384) return;
    int l = wid >> 7;
    const float* wo = Wo + (size_t)wid * 128;
    float s = 0.f;
#pragma unroll
    for (int q = 0; q < 4; q++) s += wo[lane + q * 32] * bv[l * 128 + lane + q * 32];
#pragma unroll
    for (int o = 16; o; o >>= 1) s += __shfl_xor_sync(0xffffffffu, s, o);
    if (lane == 0) g_bc[wid] = s + bo[wid];
}

// ---------------------------------------------------------------------------
// Persistent mega-kernel: all 6 sublayers as dynamic work items.
__global__ __launch_bounds__(512, 1)
void mega(const float* __restrict__ x, const float* __restrict__ Win,
          const float* __restrict__ b_in,
          const float* __restrict__ b1, const float* __restrict__ b2,
          const float* __restrict__ ln1g, const float* __restrict__ ln1b,
          const float* __restrict__ ln2g, const float* __restrict__ ln2b,
          const float* __restrict__ Wd, const float* __restrict__ bd,
          int N, int ntiles) {
    extern __shared__ __align__(256) unsigned char smem[];
    const int tid = threadIdx.x, w = tid >> 5, lane = tid & 31;
    const int wr = w >> 1, wc = w & 1, r0 = wr * 32;
    const uint32_t sb = smem_u32(smem);

    float* baS  = (float*)(smem + BA_OFF);
    float* bbS  = (float*)(smem + BB_OFF);
    float* lngS = (float*)(smem + LNG_OFF);
    float* lnbS = (float*)(smem + LNB_OFF);
    float2* red = (float2*)(smem + RED_OFF);
    float* zred = (float*)(smem + ZRED_OFF);
    float* WdS  = (float*)(smem + WD_OFF);
    int* shitem = (int*)(smem + ITEM_OFF);

    const uint32_t loff272 = (lane & 15) * 272 + (lane >> 4) * 16;
    const uint32_t loff144 = (lane & 15) * 144 + (lane >> 4) * 16;
    const uint32_t haA = sb + HA_OFF + r0 * 272 + loff272;

    for (;;) {
        if (tid == 0) *shitem = atomicAdd(&g_ctr, 1);
        __syncthreads();
        const int item = *shitem;
        if (item >= 6 * ntiles) return;
        const int s = item / ntiles;
        const int t = item - s * ntiles;
        const int layer = s >> 1;
        const int single = ((s & 1) == 0) ? 1 : 0;
        const int row0 = t * BR;
        const int F = single ? 128 : 2048;
        const int nch = F >> 6;

        const __half* Wa;
        const __half* Wb = nullptr;
        const float* ba = nullptr;
        const float *bbp, *lngp, *lnbp;
        if (single) {
            Wa = g_wh + OWC + (size_t)layer * 16384;
            bbp = g_bc + layer * 128; lngp = ln1g + layer * 128; lnbp = ln1b + layer * 128;
        } else {
            Wa = g_wh + OW1 + (size_t)layer * 262144;
            Wb = g_wh + OW2 + (size_t)layer * 262144;
            ba = b1 + layer * 2048;
            bbp = b2 + layer * 128; lngp = ln2g + layer * 128; lnbp = ln2b + layer * 128;
        }

        // dependency wait
        if (s > 0 && tid == 0) {
            while (atomicAdd(&g_done[(s - 1) * ntiles + t], 0) == 0) __nanosleep(64);
            __threadfence();
        }
        __syncthreads();

        // ---- first weight copies ----
        if (single) {
            for (int i = tid; i < 2048; i += 512) {
                int r = i >> 4, q = i & 15;
                cp16h(sb + SLOTS_OFF + r * 272 + q * 16, Wa + (size_t)r * 128 + q * 8);
            }
        } else {
            for (int i = tid; i < 1024; i += 512) {
                int r = i >> 4, q = i & 15;
                cp16h(sb + SLOTS_OFF + r * 272 + q * 16, Wa + (size_t)r * 128 + q * 8);
            }
            for (int i = tid; i < 1024; i += 512) {
                int r = i >> 3, q = i & 7;
                cp16h(sb + SLOTS_OFF + SL_SZ + r * 144 + q * 16, Wb + (size_t)r * F + q * 8);
            }
        }
        cp_commit();

        // ---- stage hA ----
        if (s == 0) {
            float* WinS = baS;            // 384 floats
            float* binS = baS + 384;      // 128 floats
            float* xS   = (float*)(smem + RED_OFF);  // 768 floats
            for (int i = tid; i < 512; i += 512) {
                if (i < 384) WinS[i] = Win[i];
                else binS[i - 384] = b_in[i - 384];
            }
            for (int i = tid; i < 768; i += 512) {
                int gi = row0 * 3 + i;
                xS[i] = (gi < N * 3) ? x[gi] : 0.f;
            }
            __syncthreads();
            for (int i = tid; i < BR * 64; i += 512) {
                int r = i >> 6, j = i & 63, c = 2 * j;
                int gr = row0 + r;
                float v0 = 0.f, v1 = 0.f;
                if (gr < N) {
                    float x0 = xS[r * 3], x1 = xS[r * 3 + 1], x2 = xS[r * 3 + 2];
                    v0 = fmaxf(binS[c] + x0 * WinS[c * 3] + x1 * WinS[c * 3 + 1]
                               + x2 * WinS[c * 3 + 2], 0.f);
                    v1 = fmaxf(binS[c + 1] + x0 * WinS[(c + 1) * 3] + x1 * WinS[(c + 1) * 3 + 1]
                               + x2 * WinS[(c + 1) * 3 + 2], 0.f);
                    *(float2*)(g_h + (size_t)gr * D + c) = make_float2(v0, v1);
                }
                __half2 h2 = __floats2half2_rn(v0, v1);
                *(uint32_t*)(smem + HA_OFF + r * 272 + j * 4) = *(uint32_t*)&h2;
            }
        } else {
            for (int i = tid; i < BR * 64; i += 512) {
                int r = i >> 6, j = i & 63;
                int gr = row0 + r;
                float2 v = make_float2(0.f, 0.f);
                if (gr < N) v = *(const float2*)(g_h + (size_t)gr * D + j * 2);
                __half2 h2 = __floats2half2_rn(v.x, v.y);
                *(uint32_t*)(smem + HA_OFF + r * 272 + j * 4) = *(uint32_t*)&h2;
            }
        }
        if (!single)
            for (int i = tid; i < F; i += 512) baS[i] = ba[i];
        for (int i = tid; i < 128; i += 512) {
            bbS[i] = bbp[i]; lngS[i] = lngp[i]; lnbS[i] = lnbp[i];
        }
        if (s == 5) {
            for (int i = tid; i < 128; i += 512) WdS[i] = Wd[i];
            if (tid == 0) WdS[128] = bd[0];
        }

        float acc[2][8][4];
#pragma unroll
        for (int m = 0; m < 2; m++)
#pragma unroll
            for (int n = 0; n < 8; n++)
#pragma unroll
                for (int e = 0; e < 4; e++) acc[m][n][e] = 0.f;

        if (single) {
            cp_wait<0>();
            __syncthreads();
            const uint32_t bB = sb + SLOTS_OFF + (wc * 64) * 272 + loff272;
            uint32_t a[2][4], b[4][4];
#pragma unroll
            for (int kk = 0; kk < 8; kk++) {
                ldsm4(a[0], haA + kk * 32);
                ldsm4(a[1], haA + 16 * 272 + kk * 32);
#pragma unroll
                for (int g = 0; g < 4; g++) ldsm4(b[g], bB + g * 16 * 272 + kk * 32);
#pragma unroll
                for (int m = 0; m < 2; m++)
#pragma unroll
                    for (int n = 0; n < 8; n++)
                        mma16816(acc[m][n], a[m], b[n >> 1][n & 1], b[n >> 1][(n & 1) + 2]);
            }
        } else {
            for (int ch = 0; ch < nch; ch++) {
                const int f0 = ch << 6;
                const uint32_t sWa = sb + SLOTS_OFF + (ch & 1) * SL_PAIR;
                const uint32_t sWb = sWa + SL_SZ;

                cp_wait<0>();
                __syncthreads();

                if (ch + 1 < nch) {
                    uint32_t nWa = sb + SLOTS_OFF + ((ch + 1) & 1) * SL_PAIR;
                    uint32_t nWb = nWa + SL_SZ;
                    const __half* srcA = Wa + (size_t)(f0 + 64) * 128;
                    const __half* srcB = Wb + (f0 + 64);
                    for (int i = tid; i < 1024; i += 512) {
                        int r = i >> 4, q = i & 15;
                        cp16h(nWa + r * 272 + q * 16, srcA + (size_t)r * 128 + q * 8);
                    }
                    for (int i = tid; i < 1024; i += 512) {
                        int r = i >> 3, q = i & 7;
                        cp16h(nWb + r * 144 + q * 16, srcB + (size_t)r * F + q * 8);
                    }
                }
                cp_commit();

                // stage 1
                float rf[2][4][4];
#pragma unroll
                for (int m = 0; m < 2; m++)
#pragma unroll
                    for (int n = 0; n < 4; n++)
#pragma unroll
                        for (int e = 0; e < 4; e++) rf[m][n][e] = 0.f;
                {
                    const uint32_t bB = sWa + (wc * 32) * 272 + loff272;
                    uint32_t a[2][4], b[2][4];
#pragma unroll
                    for (int kk = 0; kk < 8; kk++) {
                        ldsm4(a[0], haA + kk * 32);
                        ldsm4(a[1], haA + 16 * 272 + kk * 32);
                        ldsm4(b[0], bB + kk * 32);
                        ldsm4(b[1], bB + 16 * 272 + kk * 32);
#pragma unroll
                        for (int m = 0; m < 2; m++)
#pragma unroll
                            for (int n = 0; n < 4; n++)
                                mma16816(rf[m][n], a[m], b[n >> 1][n & 1], b[n >> 1][(n & 1) + 2]);
                    }
                }
                // mid: bias + relu + pack
#pragma unroll
                for (int m = 0; m < 2; m++)
#pragma unroll
                    for (int n = 0; n < 4; n++) {
                        int c = wc * 32 + n * 8 + (lane & 3) * 2;
                        float2 bias = *(const float2*)&baS[f0 + c];
                        int rowb = r0 + m * 16 + (lane >> 2);
                        __half2 p0 = __floats2half2_rn(fmaxf(rf[m][n][0] + bias.x, 0.f),
                                                       fmaxf(rf[m][n][1] + bias.y, 0.f));
                        *(uint32_t*)(smem + RS_OFF + rowb * 144 + c * 2) = *(uint32_t*)&p0;
                        __half2 p1 = __floats2half2_rn(fmaxf(rf[m][n][2] + bias.x, 0.f),
                                                       fmaxf(rf[m][n][3] + bias.y, 0.f));
                        *(uint32_t*)(smem + RS_OFF + (rowb + 8) * 144 + c * 2) = *(uint32_t*)&p1;
                    }
                asm volatile("bar.sync %0, 64;" :: "r"(1 + wr) : "memory");

                // stage 2
                {
                    const uint32_t aB = sb + RS_OFF + r0 * 144 + loff144;
                    const uint32_t bB = sWb + (wc * 64) * 144 + loff144;
                    uint32_t a[2][4], b[4][4];
#pragma unroll
                    for (int kk = 0; kk < 4; kk++) {
                        ldsm4(a[0], aB + kk * 32);
                        ldsm4(a[1], aB + 16 * 144 + kk * 32);
#pragma unroll
                        for (int g = 0; g < 4; g++) ldsm4(b[g], bB + g * 16 * 144 + kk * 32);
#pragma unroll
                        for (int m = 0; m < 2; m++)
#pragma unroll
                            for (int n = 0; n < 8; n++)
                                mma16816(acc[m][n], a[m], b[n >> 1][n & 1], b[n >> 1][(n & 1) + 2]);
                    }
                }
            }
        }

        // ---- epilogue ----
#pragma unroll
        for (int m = 0; m < 2; m++)
#pragma unroll
            for (int h = 0; h < 2; h++) {
                int lr = r0 + m * 16 + (lane >> 2) + h * 8;
                int gr = row0 + lr;
                float ss = 0.f, qq = 0.f;
                if (gr < N) {
#pragma unroll
                    for (int n = 0; n < 8; n++) {
                        int c = wc * 64 + n * 8 + (lane & 3) * 2;
                        float2 ho = *(const float2*)(g_h + (size_t)gr * D + c);
                        float v0 = acc[m][n][h * 2 + 0] + ho.x + bbS[c];
                        float v1 = acc[m][n][h * 2 + 1] + ho.y + bbS[c + 1];
                        ss += v0 + v1;
                        qq += v0 * v0 + v1 * v1;
                    }
                }
                ss += __shfl_xor_sync(0xffffffffu, ss, 1);
                ss += __shfl_xor_sync(0xffffffffu, ss, 2);
                qq += __shfl_xor_sync(0xffffffffu, qq, 1);
                qq += __shfl_xor_sync(0xffffffffu, qq, 2);
                if ((lane & 3) == 0) red[lr * 2 + wc] = make_float2(ss, qq);
            }
        asm volatile("bar.sync %0, 64;" :: "r"(1 + wr) : "memory");
#pragma unroll
        for (int m = 0; m < 2; m++)
#pragma unroll
            for (int h = 0; h < 2; h++) {
                int lr = r0 + m * 16 + (lane >> 2) + h * 8;
                int gr = row0 + lr;
                float zp = 0.f;
                if (gr < N) {
                    float2 p0 = red[lr * 2 + 0], p1 = red[lr * 2 + 1];
                    float mean = (p0.x + p1.x) * (1.f / 128.f);
                    float inv = rsqrtf((p0.y + p1.y) * (1.f / 128.f) - mean * mean + 1e-5f);
#pragma unroll
                    for (int n = 0; n < 8; n++) {
                        int c = wc * 64 + n * 8 + (lane & 3) * 2;
                        float2 ho = *(const float2*)(g_h + (size_t)gr * D + c);
                        float v0 = acc[m][n][h * 2 + 0] + ho.x + bbS[c];
                        float v1 = acc[m][n][h * 2 + 1] + ho.y + bbS[c + 1];
                        float o0 = (v0 - mean) * inv * lngS[c] + lnbS[c];
                        float o1 = (v1 - mean) * inv * lngS[c + 1] + lnbS[c + 1];
                        if (s != 5) {
                            *(float2*)(g_h + (size_t)gr * D + c) = make_float2(o0, o1);
                        } else {
                            zp += o0 * WdS[c] + o1 * WdS[c + 1];
                        }
                    }
                }
                if (s == 5) {
                    zp += __shfl_xor_sync(0xffffffffu, zp, 1);
                    zp += __shfl_xor_sync(0xffffffffu, zp, 2);
                    if ((lane & 3) == 0) zred[lr * 2 + wc] = zp;
                }
            }
        if (s == 5) {
            asm volatile("bar.sync %0, 64;" :: "r"(1 + wr) : "memory");
#pragma unroll
            for (int m = 0; m < 2; m++)
#pragma unroll
                for (int h = 0; h < 2; h++) {
                    int lr = r0 + m * 16 + (lane >> 2) + h * 8;
                    int gr = row0 + lr;
                    if (gr < N && (lane & 3) == 0 && wc == 0)
                        g_z[gr] = fmaxf(zred[lr * 2] + zred[lr * 2 + 1] + WdS[128], 0.f);
                }
        }

        __threadfence();
        __syncthreads();
        if (tid == 0) atomicExch(&g_done[s * ntiles + t], 1);
    }
}

// ---------------------------------------------------------------------------
__global__ void k_deg_init(int N) {
    int n = blockIdx.x * blockDim.x + threadIdx.x;
    if (n < N) g_deg[n] = 1.0f;
}
__global__ void k_deg_count(const int* __restrict__ col, int E) {
    int e = blockIdx.x * blockDim.x + threadIdx.x;
    if (e < E) atomicAdd(&g_deg[col[e]], 1.0f);
}
__global__ void k_dis_u(int N) {
    int n = blockIdx.x * blockDim.x + threadIdx.x;
    if (n >= N) return;
    float dis = rsqrtf(fmaxf(g_deg[n], 1.0f));
    float u = g_z[n] * dis;
    g_dis[n] = dis;
    g_u[n] = u;
    g_t[n] = u;
}
__global__ void k_scatter(const int* __restrict__ row, const int* __restrict__ col, int E) {
    int e = blockIdx.x * blockDim.x + threadIdx.x;
    if (e < E) atomicAdd(&g_t[col[e]], g_u[row[e]]);
}
__global__ void k_out(const float* __restrict__ Wg, const float* __restrict__ bg,
                      const float* __restrict__ Wf, const float* __restrict__ bf,
                      float* __restrict__ out, int N) {
    int n = blockIdx.x * blockDim.x + threadIdx.x;
    if (n >= N) return;
    float s = g_dis[n] * g_t[n];
    float a = bf[0];
#pragma unroll
    for (int k = 0; k < 32; k++)
        a += fmaxf(s * Wg[k] + bg[k], 0.f) * Wf[k];
    out[n] = a;
}

// ---------------------------------------------------------------------------
extern "C" void kernel_launch(void* const* d_in, const int* in_sizes, int n_in,
                              void* d_out, int out_size) {
    const float* x    = (const float*)d_in[0];
    const int*   edge = (const int*)  d_in[1];
    const float* Win  = (const float*)d_in[2];
    const float* b_in = (const float*)d_in[3];
    const float* Wv   = (const float*)d_in[4];
    const float* bv   = (const float*)d_in[5];
    const float* Wo   = (const float*)d_in[6];
    const float* bo   = (const float*)d_in[7];
    const float* W1   = (const float*)d_in[8];
    const float* b1   = (const float*)d_in[9];
    const float* W2   = (const float*)d_in[10];
    const float* b2   = (const float*)d_in[11];
    const float* ln1g = (const float*)d_in[12];
    const float* ln1b = (const float*)d_in[13];
    const float* ln2g = (const float*)d_in[14];
    const float* ln2b = (const float*)d_in[15];
    const float* Wd   = (const float*)d_in[16];
    const float* bd   = (const float*)d_in[17];
    const float* Wg   = (const float*)d_in[18];
    const float* bg   = (const float*)d_in[19];
    const float* Wf   = (const float*)d_in[20];
    const float* bf   = (const float*)d_in[21];

    const int N = in_sizes[0] / 3;
    const int E = in_sizes[1] / 2;
    const int ntiles = (N + BR - 1) / BR;

    __half* wh;
    cudaGetSymbolAddress((void**)&wh, g_wh);

    int sms = 148;
    cudaDeviceGetAttribute(&sms, cudaDevAttrMultiProcessorCount, 0);

    cudaFuncSetAttribute(mega, cudaFuncAttributeMaxDynamicSharedMemorySize, SMEM_BYTES);

    k_reset<<<(6 * MAXT + 511) / 512, 512>>>();
    k_cvt_h<<<(786432 + 255) / 256, 256>>>(W1, wh + OW1, 786432);
    k_cvt_h<<<(786432 + 255) / 256, 256>>>(W2, wh + OW2, 786432);
    k_wc<<<384, 128>>>(Wo, Wv);
    k_bc2<<<48, 256>>>(Wo, bv, bo);

    mega<<<sms, 512, SMEM_BYTES>>>(x, Win, b_in, b1, b2, ln1g, ln1b, ln2g, ln2b,
                                   Wd, bd, N, ntiles);

    k_deg_init<<<(N + 255) / 256, 256>>>(N);
    k_deg_count<<<(E + 255) / 256, 256>>>(edge + E, E);
    k_dis_u<<<(N + 255) / 256, 256>>>(N);
    k_scatter<<<(E + 255) / 256, 256>>>(edge, edge + E, E);
    k_out<<<(N + 255) / 256, 256>>>(Wg, bg, Wf, bf, (float*)d_out, N);
}

// round 10
// speedup vs baseline: 2.0757x; 1.1583x over previous
#include <cuda_runtime.h>
#include <cuda_fp16.h>
#include <cstdint>

#define NMAX 200000
#define D 128
#define BR 256
#define MAXT 800
#define DEGI 296

// ---- smem layout (bytes) ----
#define HA_OFF    0        // hA: 256 x 272B
#define RS_OFF    69632    // rS: 256 x 144B
#define SLOTS_OFF 106496   // 2 pairs x (18432 + 18432); Wc uses pair0 (34816B)
#define BA_OFF    180224   // b1 (2048 f); also Win(384)+b_in(128) during s-staging
#define BB_OFF    188416   // attn bias (bc)
#define LNG_OFF   188928
#define LNB_OFF   189440
#define BB2_OFF   189952   // ffn final bias (b2)
#define LNG2_OFF  190464
#define LNB2_OFF  190976
#define RED_OFF   191488   // LN partials float2[256][2]; xS (768 f) during s==0 staging
#define ZRED_OFF  195584
#define WD_OFF    197632   // Wd 128 + bd
#define ITEM_OFF  198152
static const int SMEM_BYTES = 198160;
#define SL_PAIR 36864
#define SL_SZ   18432

__device__ float g_h[(size_t)NMAX * D];
__device__ float g_z[NMAX];
__device__ float g_deg[NMAX];
__device__ float g_dis[NMAX];
__device__ float g_u[NMAX];
__device__ float g_t[NMAX];
__device__ __half g_wh[1622016];  // [W1 3x262144 | W2 3x262144 | Wc 3x16384]
__device__ float g_bc[384];
__device__ int g_ctr;
__device__ int g_done[3 * MAXT];
#define OW1 0
#define OW2 786432
#define OWC 1572864

// ---------------------------------------------------------------------------
static __device__ __forceinline__ uint32_t smem_u32(const void* p) {
    uint32_t r;
    asm("{ .reg .u64 t; cvta.to.shared.u64 t, %1; cvt.u32.u64 %0, t; }" : "=r"(r) : "l"(p));
    return r;
}
static __device__ __forceinline__ void cp16h(uint32_t dst, const __half* src) {
    asm volatile("cp.async.cg.shared.global [%0], [%1], 16;\n" :: "r"(dst), "l"(src));
}
static __device__ __forceinline__ void cp_commit() { asm volatile("cp.async.commit_group;\n"); }
template <int NPEND>
static __device__ __forceinline__ void cp_wait() { asm volatile("cp.async.wait_group %0;\n" :: "n"(NPEND)); }

static __device__ __forceinline__ void ldsm4(uint32_t* r, uint32_t addr) {
    asm volatile("ldmatrix.sync.aligned.m8n8.x4.shared.b16 {%0,%1,%2,%3}, [%4];"
                 : "=r"(r[0]), "=r"(r[1]), "=r"(r[2]), "=r"(r[3]) : "r"(addr));
}
static __device__ __forceinline__ void mma16816(float* c, const uint32_t* a,
                                                uint32_t b0, uint32_t b1) {
    asm volatile("mma.sync.aligned.m16n8k16.row.col.f32.f16.f16.f32 "
                 "{%0,%1,%2,%3}, {%4,%5,%6,%7}, {%8,%9}, {%0,%1,%2,%3};"
                 : "+f"(c[0]), "+f"(c[1]), "+f"(c[2]), "+f"(c[3])
                 : "r"(a[0]), "r"(a[1]), "r"(a[2]), "r"(a[3]), "r"(b0), "r"(b1));
}

// ---------------------------------------------------------------------------
__global__ void k_reset() {
    int i = blockIdx.x * blockDim.x + threadIdx.x;
    if (i == 0) g_ctr = 0;
    if (i < 3 * MAXT) g_done[i] = 0;
}

__global__ void k_cvt_h(const float* __restrict__ src, __half* __restrict__ dst, int n) {
    int i = blockIdx.x * blockDim.x + threadIdx.x;
    if (i < n) dst[i] = __float2half_rn(src[i]);
}

__global__ void k_wc(const float* __restrict__ Wo, const float* __restrict__ Wv) {
    int l = blockIdx.x >> 7, o = blockIdx.x & 127, d = threadIdx.x;
    const float* wo = Wo + (size_t)(l * 128 + o) * 128;
    const float* wv = Wv + (size_t)l * 128 * 128;
    float s = 0.f;
#pragma unroll 8
    for (int k = 0; k < 128; k++) s += wo[k] * wv[k * 128 + d];
    g_wh[OWC + (size_t)(l * 128 + o) * 128 + d] = __float2half_rn(s);
}

__global__ void k_bc2(const float* __restrict__ Wo, const float* __restrict__ bv,
                      const float* __restrict__ bo) {
    int wid = (blockIdx.x * blockDim.x + threadIdx.x) >> 5;
    int lane = threadIdx.x & 31;
    if (wid >= 384) return;
    int l = wid >> 7;
    const float* wo = Wo + (size_t)wid * 128;
    float s = 0.f;
#pragma unroll
    for (int q = 0; q < 4; q++) s += wo[lane + q * 32] * bv[l * 128 + lane + q * 32];
#pragma unroll
    for (int o = 16; o; o >>= 1) s += __shfl_xor_sync(0xffffffffu, s, o);
    if (lane == 0) g_bc[wid] = s + bo[wid];
}

__global__ void k_deg_init(int N) {
    int n = blockIdx.x * blockDim.x + threadIdx.x;
    if (n < N) g_deg[n] = 1.0f;
}

// ---------------------------------------------------------------------------
// Persistent mega-kernel: 3 fused (attn+FFN) layer stages + trailing deg items.
__global__ __launch_bounds__(512, 1)
void mega(const float* __restrict__ x, const float* __restrict__ Win,
          const float* __restrict__ b_in,
          const float* __restrict__ b1, const float* __restrict__ b2,
          const float* __restrict__ ln1g, const float* __restrict__ ln1b,
          const float* __restrict__ ln2g, const float* __restrict__ ln2b,
          const float* __restrict__ Wd, const float* __restrict__ bd,
          const int* __restrict__ colE, int E, int N, int ntiles) {
    extern __shared__ __align__(256) unsigned char smem[];
    const int tid = threadIdx.x, w = tid >> 5, lane = tid & 31;
    const int wr = w >> 1, wc = w & 1, r0 = wr * 32;
    const uint32_t sb = smem_u32(smem);
    const int NT3 = 3 * ntiles;

    float* baS   = (float*)(smem + BA_OFF);
    float* bbS   = (float*)(smem + BB_OFF);
    float* lngS  = (float*)(smem + LNG_OFF);
    float* lnbS  = (float*)(smem + LNB_OFF);
    float* bb2S  = (float*)(smem + BB2_OFF);
    float* lng2S = (float*)(smem + LNG2_OFF);
    float* lnb2S = (float*)(smem + LNB2_OFF);
    float2* red  = (float2*)(smem + RED_OFF);
    float* zred  = (float*)(smem + ZRED_OFF);
    float* WdS   = (float*)(smem + WD_OFF);
    int* shitem  = (int*)(smem + ITEM_OFF);

    const uint32_t loff272 = (lane & 15) * 272 + (lane >> 4) * 16;
    const uint32_t loff144 = (lane & 15) * 144 + (lane >> 4) * 16;
    const uint32_t haA = sb + HA_OFF + r0 * 272 + loff272;

    for (;;) {
        if (tid == 0) *shitem = atomicAdd(&g_ctr, 1);
        __syncthreads();
        const int item = *shitem;
        if (item >= NT3 + DEGI) return;
        if (item >= NT3) {
            // degree-count slice (independent; fills tail)
            int di = item - NT3;
            int slice = (E + DEGI - 1) / DEGI;
            int e0 = di * slice;
            int e1 = e0 + slice; if (e1 > E) e1 = E;
            for (int e = e0 + tid; e < e1; e += 512)
                atomicAdd(&g_deg[colE[e]], 1.0f);
            continue;
        }
        const int s = item / ntiles;
        const int t = item - s * ntiles;
        const int row0 = t * BR;

        const __half* Wc = g_wh + OWC + (size_t)s * 16384;
        const __half* Wa = g_wh + OW1 + (size_t)s * 262144;
        const __half* Wb = g_wh + OW2 + (size_t)s * 262144;

        if (s > 0 && tid == 0) {
            while (atomicAdd(&g_done[(s - 1) * ntiles + t], 0) == 0) __nanosleep(64);
            __threadfence();
        }
        __syncthreads();

        // G1: Wc -> pair0
        for (int i = tid; i < 2048; i += 512) {
            int r = i >> 4, q = i & 15;
            cp16h(sb + SLOTS_OFF + r * 272 + q * 16, Wc + (size_t)r * 128 + q * 8);
        }
        cp_commit();
        // G2: FFN chunk0 -> pair1
        for (int i = tid; i < 1024; i += 512) {
            int r = i >> 4, q = i & 15;
            cp16h(sb + SLOTS_OFF + SL_PAIR + r * 272 + q * 16, Wa + (size_t)r * 128 + q * 8);
        }
        for (int i = tid; i < 1024; i += 512) {
            int r = i >> 3, q = i & 7;
            cp16h(sb + SLOTS_OFF + SL_PAIR + SL_SZ + r * 144 + q * 16,
                  Wb + (size_t)r * 2048 + q * 8);
        }
        cp_commit();

        // ---- stage hA ----
        if (s == 0) {
            float* WinS = baS;
            float* binS = baS + 384;
            float* xS   = (float*)(smem + RED_OFF);
            if (tid < 384) WinS[tid] = Win[tid];
            else if (tid < 512) binS[tid - 384] = b_in[tid - 384];
            for (int i = tid; i < 768; i += 512) {
                int gi = row0 * 3 + i;
                xS[i] = (gi < N * 3) ? x[gi] : 0.f;
            }
            __syncthreads();
            for (int i = tid; i < BR * 64; i += 512) {
                int r = i >> 6, j = i & 63, c = 2 * j;
                int gr = row0 + r;
                float v0 = 0.f, v1 = 0.f;
                if (gr < N) {
                    float x0 = xS[r * 3], x1 = xS[r * 3 + 1], x2 = xS[r * 3 + 2];
                    v0 = fmaxf(binS[c] + x0 * WinS[c * 3] + x1 * WinS[c * 3 + 1]
                               + x2 * WinS[c * 3 + 2], 0.f);
                    v1 = fmaxf(binS[c + 1] + x0 * WinS[(c + 1) * 3] + x1 * WinS[(c + 1) * 3 + 1]
                               + x2 * WinS[(c + 1) * 3 + 2], 0.f);
                }
                __half2 h2 = __floats2half2_rn(v0, v1);
                *(uint32_t*)(smem + HA_OFF + r * 272 + j * 4) = *(uint32_t*)&h2;
            }
        } else {
            for (int i = tid; i < BR * 64; i += 512) {
                int r = i >> 6, j = i & 63;
                int gr = row0 + r;
                float2 v = make_float2(0.f, 0.f);
                if (gr < N) v = *(const float2*)(g_h + (size_t)gr * D + j * 2);
                __half2 h2 = __floats2half2_rn(v.x, v.y);
                *(uint32_t*)(smem + HA_OFF + r * 272 + j * 4) = *(uint32_t*)&h2;
            }
        }
        // biases (both sets)
        if (tid < 128) {
            bbS[tid]   = g_bc[s * 128 + tid];
            lngS[tid]  = ln1g[s * 128 + tid];
            lnbS[tid]  = ln1b[s * 128 + tid];
            bb2S[tid]  = b2[s * 128 + tid];
            lng2S[tid] = ln2g[s * 128 + tid];
            lnb2S[tid] = ln2b[s * 128 + tid];
        }
        if (s == 2) {
            if (tid < 128) WdS[tid] = Wd[tid];
            if (tid == 128) WdS[128] = bd[0];
        }

        cp_wait<1>();     // Wc landed (chunk0 may fly)
        __syncthreads();  // hA + biases visible; WinS area now dead

        // load b1 into baS (visible by FFN-loop's first __syncthreads)
        for (int i = tid; i < 2048; i += 512) baS[i] = b1[s * 2048 + i];

        float acc[2][8][4];
#pragma unroll
        for (int m = 0; m < 2; m++)
#pragma unroll
            for (int n = 0; n < 8; n++)
#pragma unroll
                for (int e = 0; e < 4; e++) acc[m][n][e] = 0.f;

        // ======== attn GEMM: acc = hA @ Wc^T ========
        {
            const uint32_t bB = sb + SLOTS_OFF + (wc * 64) * 272 + loff272;
            uint32_t a[2][4], b[4][4];
#pragma unroll
            for (int kk = 0; kk < 8; kk++) {
                ldsm4(a[0], haA + kk * 32);
                ldsm4(a[1], haA + 16 * 272 + kk * 32);
#pragma unroll
                for (int g = 0; g < 4; g++) ldsm4(b[g], bB + g * 16 * 272 + kk * 32);
#pragma unroll
                for (int m = 0; m < 2; m++)
#pragma unroll
                    for (int n = 0; n < 8; n++)
                        mma16816(acc[m][n], a[m], b[n >> 1][n & 1], b[n >> 1][(n & 1) + 2]);
            }
        }
        __syncthreads();  // all warps done reading Wc (pair0) and hA for attn

        // ======== attn epilogue: LN1, write back into hA (fp16) ========
#pragma unroll
        for (int m = 0; m < 2; m++)
#pragma unroll
            for (int h = 0; h < 2; h++) {
                int lr = r0 + m * 16 + (lane >> 2) + h * 8;
                int gr = row0 + lr;
                float ss = 0.f, qq = 0.f;
                if (gr < N) {
#pragma unroll
                    for (int n = 0; n < 8; n++) {
                        int c = wc * 64 + n * 8 + (lane & 3) * 2;
                        __half2 hh = *(__half2*)(smem + HA_OFF + lr * 272 + c * 2);
                        float2 ho = __half22float2(hh);
                        float v0 = acc[m][n][h * 2 + 0] + ho.x + bbS[c];
                        float v1 = acc[m][n][h * 2 + 1] + ho.y + bbS[c + 1];
                        ss += v0 + v1;
                        qq += v0 * v0 + v1 * v1;
                    }
                }
                ss += __shfl_xor_sync(0xffffffffu, ss, 1);
                ss += __shfl_xor_sync(0xffffffffu, ss, 2);
                qq += __shfl_xor_sync(0xffffffffu, qq, 1);
                qq += __shfl_xor_sync(0xffffffffu, qq, 2);
                if ((lane & 3) == 0) red[lr * 2 + wc] = make_float2(ss, qq);
            }
        asm volatile("bar.sync %0, 64;" :: "r"(1 + wr) : "memory");
#pragma unroll
        for (int m = 0; m < 2; m++)
#pragma unroll
            for (int h = 0; h < 2; h++) {
                int lr = r0 + m * 16 + (lane >> 2) + h * 8;
                int gr = row0 + lr;
                if (gr >= N) continue;
                float2 p0 = red[lr * 2 + 0], p1 = red[lr * 2 + 1];
                float mean = (p0.x + p1.x) * (1.f / 128.f);
                float inv = rsqrtf((p0.y + p1.y) * (1.f / 128.f) - mean * mean + 1e-5f);
#pragma unroll
                for (int n = 0; n < 8; n++) {
                    int c = wc * 64 + n * 8 + (lane & 3) * 2;
                    __half2 hh = *(__half2*)(smem + HA_OFF + lr * 272 + c * 2);
                    float2 ho = __half22float2(hh);
                    float v0 = acc[m][n][h * 2 + 0] + ho.x + bbS[c];
                    float v1 = acc[m][n][h * 2 + 1] + ho.y + bbS[c + 1];
                    float o0 = (v0 - mean) * inv * lngS[c] + lnbS[c];
                    float o1 = (v1 - mean) * inv * lngS[c + 1] + lnbS[c + 1];
                    __half2 oo = __floats2half2_rn(o0, o1);
                    *(uint32_t*)(smem + HA_OFF + lr * 272 + c * 2) = *(uint32_t*)&oo;
                }
            }
        // re-zero acc for FFN
#pragma unroll
        for (int m = 0; m < 2; m++)
#pragma unroll
            for (int n = 0; n < 8; n++)
#pragma unroll
                for (int e = 0; e < 4; e++) acc[m][n][e] = 0.f;

        // ======== FFN: 32 chunks; chunk c lives in pair ((c+1)&1) ========
        for (int ch = 0; ch < 32; ch++) {
            const int f0 = ch << 6;
            const uint32_t sWa = sb + SLOTS_OFF + (((ch + 1) & 1)) * SL_PAIR;
            const uint32_t sWb = sWa + SL_SZ;

            cp_wait<0>();
            __syncthreads();

            if (ch + 1 < 32) {
                uint32_t nWa = sb + SLOTS_OFF + ((ch & 1)) * SL_PAIR;
                uint32_t nWb = nWa + SL_SZ;
                const __half* srcA = Wa + (size_t)(f0 + 64) * 128;
                const __half* srcB = Wb + (f0 + 64);
                for (int i = tid; i < 1024; i += 512) {
                    int r = i >> 4, q = i & 15;
                    cp16h(nWa + r * 272 + q * 16, srcA + (size_t)r * 128 + q * 8);
                }
                for (int i = tid; i < 1024; i += 512) {
                    int r = i >> 3, q = i & 7;
                    cp16h(nWb + r * 144 + q * 16, srcB + (size_t)r * 2048 + q * 8);
                }
            }
            cp_commit();

            // stage 1
            float rf[2][4][4];
#pragma unroll
            for (int m = 0; m < 2; m++)
#pragma unroll
                for (int n = 0; n < 4; n++)
#pragma unroll
                    for (int e = 0; e < 4; e++) rf[m][n][e] = 0.f;
            {
                const uint32_t bB = sWa + (wc * 32) * 272 + loff272;
                uint32_t a[2][4], b[2][4];
#pragma unroll
                for (int kk = 0; kk < 8; kk++) {
                    ldsm4(a[0], haA + kk * 32);
                    ldsm4(a[1], haA + 16 * 272 + kk * 32);
                    ldsm4(b[0], bB + kk * 32);
                    ldsm4(b[1], bB + 16 * 272 + kk * 32);
#pragma unroll
                    for (int m = 0; m < 2; m++)
#pragma unroll
                        for (int n = 0; n < 4; n++)
                            mma16816(rf[m][n], a[m], b[n >> 1][n & 1], b[n >> 1][(n & 1) + 2]);
                }
            }
            // mid: bias + relu + pack
#pragma unroll
            for (int m = 0; m < 2; m++)
#pragma unroll
                for (int n = 0; n < 4; n++) {
                    int c = wc * 32 + n * 8 + (lane & 3) * 2;
                    float2 bias = *(const float2*)&baS[f0 + c];
                    int rowb = r0 + m * 16 + (lane >> 2);
                    __half2 p0 = __floats2half2_rn(fmaxf(rf[m][n][0] + bias.x, 0.f),
                                                   fmaxf(rf[m][n][1] + bias.y, 0.f));
                    *(uint32_t*)(smem + RS_OFF + rowb * 144 + c * 2) = *(uint32_t*)&p0;
                    __half2 p1 = __floats2half2_rn(fmaxf(rf[m][n][2] + bias.x, 0.f),
                                                   fmaxf(rf[m][n][3] + bias.y, 0.f));
                    *(uint32_t*)(smem + RS_OFF + (rowb + 8) * 144 + c * 2) = *(uint32_t*)&p1;
                }
            asm volatile("bar.sync %0, 64;" :: "r"(1 + wr) : "memory");

            // stage 2
            {
                const uint32_t aB = sb + RS_OFF + r0 * 144 + loff144;
                const uint32_t bB = sWb + (wc * 64) * 144 + loff144;
                uint32_t a[2][4], b[4][4];
#pragma unroll
                for (int kk = 0; kk < 4; kk++) {
                    ldsm4(a[0], aB + kk * 32);
                    ldsm4(a[1], aB + 16 * 144 + kk * 32);
#pragma unroll
                    for (int g = 0; g < 4; g++) ldsm4(b[g], bB + g * 16 * 144 + kk * 32);
#pragma unroll
                    for (int m = 0; m < 2; m++)
#pragma unroll
                        for (int n = 0; n < 8; n++)
                            mma16816(acc[m][n], a[m], b[n >> 1][n & 1], b[n >> 1][(n & 1) + 2]);
                }
            }
        }

        // ======== FFN epilogue: LN2 (residual = hA fp16) ========
#pragma unroll
        for (int m = 0; m < 2; m++)
#pragma unroll
            for (int h = 0; h < 2; h++) {
                int lr = r0 + m * 16 + (lane >> 2) + h * 8;
                int gr = row0 + lr;
                float ss = 0.f, qq = 0.f;
                if (gr < N) {
#pragma unroll
                    for (int n = 0; n < 8; n++) {
                        int c = wc * 64 + n * 8 + (lane & 3) * 2;
                        __half2 hh = *(__half2*)(smem + HA_OFF + lr * 272 + c * 2);
                        float2 ho = __half22float2(hh);
                        float v0 = acc[m][n][h * 2 + 0] + ho.x + bb2S[c];
                        float v1 = acc[m][n][h * 2 + 1] + ho.y + bb2S[c + 1];
                        ss += v0 + v1;
                        qq += v0 * v0 + v1 * v1;
                    }
                }
                ss += __shfl_xor_sync(0xffffffffu, ss, 1);
                ss += __shfl_xor_sync(0xffffffffu, ss, 2);
                qq += __shfl_xor_sync(0xffffffffu, qq, 1);
                qq += __shfl_xor_sync(0xffffffffu, qq, 2);
                if ((lane & 3) == 0) red[lr * 2 + wc] = make_float2(ss, qq);
            }
        asm volatile("bar.sync %0, 64;" :: "r"(1 + wr) : "memory");
#pragma unroll
        for (int m = 0; m < 2; m++)
#pragma unroll
            for (int h = 0; h < 2; h++) {
                int lr = r0 + m * 16 + (lane >> 2) + h * 8;
                int gr = row0 + lr;
                float zp = 0.f;
                if (gr < N) {
                    float2 p0 = red[lr * 2 + 0], p1 = red[lr * 2 + 1];
                    float mean = (p0.x + p1.x) * (1.f / 128.f);
                    float inv = rsqrtf((p0.y + p1.y) * (1.f / 128.f) - mean * mean + 1e-5f);
#pragma unroll
                    for (int n = 0; n < 8; n++) {
                        int c = wc * 64 + n * 8 + (lane & 3) * 2;
                        __half2 hh = *(__half2*)(smem + HA_OFF + lr * 272 + c * 2);
                        float2 ho = __half22float2(hh);
                        float v0 = acc[m][n][h * 2 + 0] + ho.x + bb2S[c];
                        float v1 = acc[m][n][h * 2 + 1] + ho.y + bb2S[c + 1];
                        float o0 = (v0 - mean) * inv * lng2S[c] + lnb2S[c];
                        float o1 = (v1 - mean) * inv * lng2S[c + 1] + lnb2S[c + 1];
                        if (s != 2) {
                            *(float2*)(g_h + (size_t)gr * D + c) = make_float2(o0, o1);
                        } else {
                            zp += o0 * WdS[c] + o1 * WdS[c + 1];
                        }
                    }
                }
                if (s == 2) {
                    zp += __shfl_xor_sync(0xffffffffu, zp, 1);
                    zp += __shfl_xor_sync(0xffffffffu, zp, 2);
                    if ((lane & 3) == 0) zred[lr * 2 + wc] = zp;
                }
            }
        if (s == 2) {
            asm volatile("bar.sync %0, 64;" :: "r"(1 + wr) : "memory");
#pragma unroll
            for (int m = 0; m < 2; m++)
#pragma unroll
                for (int h = 0; h < 2; h++) {
                    int lr = r0 + m * 16 + (lane >> 2) + h * 8;
                    int gr = row0 + lr;
                    if (gr < N && (lane & 3) == 0 && wc == 0)
                        g_z[gr] = fmaxf(zred[lr * 2] + zred[lr * 2 + 1] + WdS[128], 0.f);
                }
        }

        __threadfence();
        __syncthreads();
        if (tid == 0 && s < 2) atomicExch(&g_done[s * ntiles + t], 1);
    }
}

// ---------------------------------------------------------------------------
__global__ void k_dis_u(int N) {
    int n = blockIdx.x * blockDim.x + threadIdx.x;
    if (n >= N) return;
    float dis = rsqrtf(fmaxf(g_deg[n], 1.0f));
    float u = g_z[n] * dis;
    g_dis[n] = dis;
    g_u[n] = u;
    g_t[n] = u;
}
__global__ void k_scatter(const int* __restrict__ row, const int* __restrict__ col, int E) {
    int e = blockIdx.x * blockDim.x + threadIdx.x;
    if (e < E) atomicAdd(&g_t[col[e]], g_u[row[e]]);
}
__global__ void k_out(const float* __restrict__ Wg, const float* __restrict__ bg,
                      const float* __restrict__ Wf, const float* __restrict__ bf,
                      float* __restrict__ out, int N) {
    int n = blockIdx.x * blockDim.x + threadIdx.x;
    if (n >= N) return;
    float s = g_dis[n] * g_t[n];
    float a = bf[0];
#pragma unroll
    for (int k = 0; k < 32; k++)
        a += fmaxf(s * Wg[k] + bg[k], 0.f) * Wf[k];
    out[n] = a;
}

// ---------------------------------------------------------------------------
extern "C" void kernel_launch(void* const* d_in, const int* in_sizes, int n_in,
                              void* d_out, int out_size) {
    const float* x    = (const float*)d_in[0];
    const int*   edge = (const int*)  d_in[1];
    const float* Win  = (const float*)d_in[2];
    const float* b_in = (const float*)d_in[3];
    const float* Wv   = (const float*)d_in[4];
    const float* bv   = (const float*)d_in[5];
    const float* Wo   = (const float*)d_in[6];
    const float* bo   = (const float*)d_in[7];
    const float* W1   = (const float*)d_in[8];
    const float* b1   = (const float*)d_in[9];
    const float* W2   = (const float*)d_in[10];
    const float* b2   = (const float*)d_in[11];
    const float* ln1g = (const float*)d_in[12];
    const float* ln1b = (const float*)d_in[13];
    const float* ln2g = (const float*)d_in[14];
    const float* ln2b = (const float*)d_in[15];
    const float* Wd   = (const float*)d_in[16];
    const float* bd   = (const float*)d_in[17];
    const float* Wg   = (const float*)d_in[18];
    const float* bg   = (const float*)d_in[19];
    const float* Wf   = (const float*)d_in[20];
    const float* bf   = (const float*)d_in[21];

    const int N = in_sizes[0] / 3;
    const int E = in_sizes[1] / 2;
    const int ntiles = (N + BR - 1) / BR;

    __half* wh;
    cudaGetSymbolAddress((void**)&wh, g_wh);

    int sms = 148;
    cudaDeviceGetAttribute(&sms, cudaDevAttrMultiProcessorCount, 0);

    cudaFuncSetAttribute(mega, cudaFuncAttributeMaxDynamicSharedMemorySize, SMEM_BYTES);

    k_reset<<<(3 * MAXT + 511) / 512, 512>>>();
    k_cvt_h<<<(786432 + 255) / 256, 256>>>(W1, wh + OW1, 786432);
    k_cvt_h<<<(786432 + 255) / 256, 256>>>(W2, wh + OW2, 786432);
    k_wc<<<384, 128>>>(Wo, Wv);
    k_bc2<<<48, 256>>>(Wo, bv, bo);
    k_deg_init<<<(N + 255) / 256, 256>>>(N);

    mega<<<sms, 512, SMEM_BYTES>>>(x, Win, b_in, b1, b2, ln1g, ln1b, ln2g, ln2b,
                                   Wd, bd, edge + E, E, N, ntiles);

    k_dis_u<<<(N + 255) / 256, 256>>>(N);
    k_scatter<<<(E + 255) / 256, 256>>>(edge, edge + E, E);
    k_out<<<(N + 255) / 256, 256>>>(Wg, bg, Wf, bf, (float*)d_out, N);
}